// round 2
// baseline (speedup 1.0000x reference)
#include <cuda_runtime.h>
#include <cuda_bf16.h>
#include <cstdint>

// Problem constants (from reference)
#define N_SAMP 131072
#define NDIM_C 512
#define NCOMP_C 256
#define NCLASS_C 8
#define NBIN_C 100

// Scratch: data0 (N x NCOMP), overwritten in-place with delta = spline(data0) - data0
__device__ float g_scratch[(size_t)N_SAMP * NCOMP_C];

// ---------------------------------------------------------------------------
// fp32 SGEMM: C[M,N] = A[M,K] * B[K,N] (+ Csrc), block tile 128x128x8,
// 256 threads, 8x8 per-thread register tile.
// B_IS_TRANSPOSED: B element B[k][j] = Bmat[j*K + k] (used for wT.T where
// wT is stored row-major [NDIM, NCOMP] and K == NCOMP).
// ---------------------------------------------------------------------------
template<bool B_IS_TRANSPOSED, bool ADD_SRC>
__global__ __launch_bounds__(256, 2)
void sgemm128(const float* __restrict__ A, const float* __restrict__ B,
              const float* __restrict__ Csrc, float* __restrict__ C,
              int M, int Ncols, int K)
{
    __shared__ float As[8][128];
    __shared__ float Bs[8][128];

    const int tid = threadIdx.x;
    const int tx  = tid & 15;      // 0..15 along N
    const int ty  = tid >> 4;      // 0..15 along M
    const int row0 = blockIdx.y * 128;
    const int col0 = blockIdx.x * 128;

    // A tile load mapping: 128x8 floats = 256 float4 -> one float4 per thread
    const int aRow = tid >> 1;            // 0..127
    const int aCol = (tid & 1) * 4;       // 0 or 4
    // B tile load mapping: 8x128 floats = 256 float4
    const int bRow = tid >> 5;            // 0..7
    const int bCol = (tid & 31) * 4;      // 0..124

    float acc[8][8];
    #pragma unroll
    for (int i = 0; i < 8; i++)
        #pragma unroll
        for (int j = 0; j < 8; j++) acc[i][j] = 0.0f;

    const float* Aptr = A + (size_t)(row0 + aRow) * K + aCol;

    for (int k0 = 0; k0 < K; k0 += 8) {
        // --- load A tile (transposed into smem: As[k][m]) ---
        float4 av = *reinterpret_cast<const float4*>(Aptr + k0);
        As[aCol + 0][aRow] = av.x;
        As[aCol + 1][aRow] = av.y;
        As[aCol + 2][aRow] = av.z;
        As[aCol + 3][aRow] = av.w;
        // --- load B tile: Bs[k][n] ---
        if (!B_IS_TRANSPOSED) {
            float4 bv = *reinterpret_cast<const float4*>(
                B + (size_t)(k0 + bRow) * Ncols + col0 + bCol);
            *reinterpret_cast<float4*>(&Bs[bRow][bCol]) = bv;
        } else {
            #pragma unroll
            for (int u = 0; u < 4; u++)
                Bs[bRow][bCol + u] = B[(size_t)(col0 + bCol + u) * K + (k0 + bRow)];
        }
        __syncthreads();

        #pragma unroll
        for (int kk = 0; kk < 8; kk++) {
            float4 a0 = *reinterpret_cast<const float4*>(&As[kk][ty * 8]);
            float4 a1 = *reinterpret_cast<const float4*>(&As[kk][ty * 8 + 4]);
            float4 b0 = *reinterpret_cast<const float4*>(&Bs[kk][tx * 8]);
            float4 b1 = *reinterpret_cast<const float4*>(&Bs[kk][tx * 8 + 4]);
            float ar[8] = {a0.x, a0.y, a0.z, a0.w, a1.x, a1.y, a1.z, a1.w};
            float br[8] = {b0.x, b0.y, b0.z, b0.w, b1.x, b1.y, b1.z, b1.w};
            #pragma unroll
            for (int i = 0; i < 8; i++)
                #pragma unroll
                for (int j = 0; j < 8; j++)
                    acc[i][j] = fmaf(ar[i], br[j], acc[i][j]);
        }
        __syncthreads();
    }

    // --- epilogue ---
    #pragma unroll
    for (int i = 0; i < 8; i++) {
        size_t r = (size_t)(row0 + ty * 8 + i) * Ncols + col0 + tx * 8;
        #pragma unroll
        for (int j = 0; j < 8; j += 4) {
            float4 v;
            v.x = acc[i][j + 0]; v.y = acc[i][j + 1];
            v.z = acc[i][j + 2]; v.w = acc[i][j + 3];
            if (ADD_SRC) {
                float4 s = *reinterpret_cast<const float4*>(Csrc + r + j);
                v.x += s.x; v.y += s.y; v.z += s.z; v.w += s.w;
            }
            *reinterpret_cast<float4*>(C + r + j) = v;
        }
    }
}

// ---------------------------------------------------------------------------
// Spline kernel: one block per sample (256 threads = 256 components).
// Reads x = data0[n,d], writes delta[n,d] = spline(x) - x (in place) and
// logj[n] = sum_d logd[n,d].
// ---------------------------------------------------------------------------
__global__ __launch_bounds__(NCOMP_C)
void spline_kernel(float* __restrict__ x_io,
                   const int* __restrict__ label,
                   const float* __restrict__ kx,
                   const float* __restrict__ ky,
                   const float* __restrict__ kd,
                   float* __restrict__ logj)
{
    const int n = blockIdx.x;
    const int d = threadIdx.x;
    const int c = label[n];

    const size_t base = ((size_t)c * NCOMP_C + d) * NBIN_C;
    const float* xr = kx + base;
    const float* yr = ky + base;
    const float* dr = kd + base;

    const size_t elem = (size_t)n * NCOMP_C + d;
    const float x = x_io[elem];

    // searchsorted (side='left'): first idx with xr[idx] >= x
    int lo = 0, hi = NBIN_C;
    while (lo < hi) {
        int mid = (lo + hi) >> 1;
        if (__ldg(xr + mid) < x) lo = mid + 1; else hi = mid;
    }

    float y, ld;
    if (lo == 0) {
        float x0 = __ldg(xr), y0 = __ldg(yr), dd = __ldg(dr);
        y  = y0 + dd * (x - x0);
        ld = __logf(dd);
    } else if (lo == NBIN_C) {
        float x1 = __ldg(xr + NBIN_C - 1), y1 = __ldg(yr + NBIN_C - 1),
              dd = __ldg(dr + NBIN_C - 1);
        y  = y1 + dd * (x - x1);
        ld = __logf(dd);
    } else {
        int k = lo - 1;
        float x0 = __ldg(xr + k), x1 = __ldg(xr + k + 1);
        float y0 = __ldg(yr + k), y1 = __ldg(yr + k + 1);
        float d0 = __ldg(dr + k), d1 = __ldg(dr + k + 1);
        float w  = x1 - x0;
        float s  = (y1 - y0) / w;
        float xi = (x - x0) / w;
        xi = fminf(fmaxf(xi, 0.0f), 1.0f);
        float xi1 = 1.0f - xi;
        float t   = xi * xi1;
        float denom = s + (d0 + d1 - 2.0f * s) * t;
        float num   = s * xi * xi + d0 * t;
        y = y0 + (y1 - y0) * num / denom;
        float num2 = d1 * xi * xi + 2.0f * s * t + d0 * xi1 * xi1;
        // 2*log(s) + log(num2) - 2*log(denom) fused into a single log
        ld = __logf(s * s * num2 / (denom * denom));
    }

    x_io[elem] = y - x;   // delta

    // block reduction of ld over 256 threads
    __shared__ float red[8];
    #pragma unroll
    for (int off = 16; off; off >>= 1)
        ld += __shfl_down_sync(0xffffffffu, ld, off);
    if ((d & 31) == 0) red[d >> 5] = ld;
    __syncthreads();
    if (d < 8) {
        float v = red[d];
        #pragma unroll
        for (int off = 4; off; off >>= 1)
            v += __shfl_down_sync(0xffu, v, off);
        if (d == 0) logj[n] = v;
    }
}

// ---------------------------------------------------------------------------
extern "C" void kernel_launch(void* const* d_in, const int* in_sizes, int n_in,
                              void* d_out, int out_size)
{
    const float* data  = (const float*)d_in[0];   // (N, 512)
    const float* wT    = (const float*)d_in[1];   // (512, 256)
    const float* kx    = (const float*)d_in[2];   // (8, 256, 100)
    const float* ky    = (const float*)d_in[3];
    const float* kd    = (const float*)d_in[4];
    const int*   label = (const int*)d_in[5];     // (N,)

    float* out  = (float*)d_out;                          // (N, 512)
    float* logj = out + (size_t)N_SAMP * NDIM_C;          // (N,)

    float* scratch = nullptr;
    cudaGetSymbolAddress((void**)&scratch, g_scratch);

    // 1) data0 = data @ wT    (M=131072, N=256, K=512)
    {
        dim3 grid(NCOMP_C / 128, N_SAMP / 128);
        sgemm128<false, false><<<grid, 256>>>(data, wT, nullptr, scratch,
                                              N_SAMP, NCOMP_C, NDIM_C);
    }

    // 2) delta = spline(data0) - data0 (in place); logj row-sums
    spline_kernel<<<N_SAMP, NCOMP_C>>>(scratch, label, kx, ky, kd, logj);

    // 3) out = data + delta @ wT.T   (M=131072, N=512, K=256)
    {
        dim3 grid(NDIM_C / 128, N_SAMP / 128);
        sgemm128<true, true><<<grid, 256>>>(scratch, wT, data, out,
                                            N_SAMP, NDIM_C, NCOMP_C);
    }
}

// round 6
// speedup vs baseline: 3.0900x; 3.0900x over previous
#include <cuda_runtime.h>
#include <cuda_bf16.h>
#include <cstdint>

#define N_SAMP 131072
#define NDIM_C 512
#define NCOMP_C 256
#define NCLASS_C 8
#define NBIN_C 100

// Scratch: data0 (N x NCOMP), overwritten in place with delta = spline(x) - x
__device__ float g_scratch[(size_t)N_SAMP * NCOMP_C];
// Pre-split B operands (bf16 hi/lo).
// GEMM1 needs B[n][k] = wT[k][n]  -> [256][512]
__device__ __nv_bfloat16 g_Bt_hi[NCOMP_C * NDIM_C];
__device__ __nv_bfloat16 g_Bt_lo[NCOMP_C * NDIM_C];
// GEMM2 needs B[j][k] = wT[j][k]  -> [512][256] (native layout)
__device__ __nv_bfloat16 g_B2_hi[NDIM_C * NCOMP_C];
__device__ __nv_bfloat16 g_B2_lo[NDIM_C * NCOMP_C];

// ---------------------------------------------------------------------------
__device__ __forceinline__ uint32_t smem_u32(const void* p) {
    uint32_t a;
    asm("{ .reg .u64 t; cvta.to.shared.u64 t, %1; cvt.u32.u64 %0, t; }"
        : "=r"(a) : "l"(p));
    return a;
}

#define SWZ128(off) ((off) ^ (((off) >> 3) & 0x70))

__device__ __forceinline__ void ldsm_x4(uint32_t* r, uint32_t addr) {
    asm volatile("ldmatrix.sync.aligned.m8n8.x4.shared.b16 {%0,%1,%2,%3}, [%4];"
                 : "=r"(r[0]), "=r"(r[1]), "=r"(r[2]), "=r"(r[3]) : "r"(addr));
}
__device__ __forceinline__ void ldsm_x2(uint32_t* r, uint32_t addr) {
    asm volatile("ldmatrix.sync.aligned.m8n8.x2.shared.b16 {%0,%1}, [%2];"
                 : "=r"(r[0]), "=r"(r[1]) : "r"(addr));
}
// D += A(16x16 bf16) * B(16x8 bf16), fp32 accum
__device__ __forceinline__ void mma_bf16(float* c, const uint32_t* a, const uint32_t* b) {
    asm volatile(
        "mma.sync.aligned.m16n8k16.row.col.f32.bf16.bf16.f32 "
        "{%0,%1,%2,%3}, {%4,%5,%6,%7}, {%8,%9}, {%0,%1,%2,%3};"
        : "+f"(c[0]), "+f"(c[1]), "+f"(c[2]), "+f"(c[3])
        : "r"(a[0]), "r"(a[1]), "r"(a[2]), "r"(a[3]), "r"(b[0]), "r"(b[1]));
}

// ---------------------------------------------------------------------------
// Prep: split wT into bf16 hi/lo in both layouts
// ---------------------------------------------------------------------------
__global__ void prep_split(const float* __restrict__ wT) {
    int i = blockIdx.x * 256 + threadIdx.x;      // over 512*256
    float v = wT[i];
    __nv_bfloat16 h = __float2bfloat16(v);
    __nv_bfloat16 l = __float2bfloat16(v - __bfloat162float(h));
    g_B2_hi[i] = h;  g_B2_lo[i] = l;             // [512][256] native
    int k = i >> 8, n = i & 255;                 // wT[k][n]
    g_Bt_hi[n * NDIM_C + k] = h;                 // [256][512] transposed
    g_Bt_lo[n * NDIM_C + k] = l;
}

// ---------------------------------------------------------------------------
// HMMA GEMM: C[M,NOUT] = A(fp32, split->bf16 hi/lo on the fly) @ B(bf16 hi/lo)^T
// A: [M][KTOT] fp32; B: [NOUT][KTOT] bf16. Block tile 128x128, K-chunk 64.
// 256 threads = 8 warps; warp tile 64x32 (4x4 m16n8k16 atoms).
// 3-product split precision: Ahi*Bhi + Ahi*Blo + Alo*Bhi, fp32 accumulate.
// ---------------------------------------------------------------------------
static constexpr int SMEM_BYTES = 65536;   // Ahi|Alo|Bhi|Blo, 16KB each (SW128)

template<int KTOT, int NOUT, bool ADD_SRC>
__global__ __launch_bounds__(256, 2)
void hmma_gemm(const float* __restrict__ A,
               const __nv_bfloat16* __restrict__ Bhi,
               const __nv_bfloat16* __restrict__ Blo,
               const float* __restrict__ Csrc,
               float* __restrict__ C)
{
    extern __shared__ char smem[];
    const uint32_t sb = smem_u32(smem);
    const int tid  = threadIdx.x;
    const int lane = tid & 31;
    const int wid  = tid >> 5;
    const int wm   = wid & 1;          // 2 warps along M (64 rows each)
    const int wn   = wid >> 1;         // 4 warps along N (32 cols each)
    const int row0 = blockIdx.y * 128;
    const int n0   = blockIdx.x * 128;

    float acc[4][4][4];
    #pragma unroll
    for (int i = 0; i < 4; i++)
        #pragma unroll
        for (int j = 0; j < 4; j++)
            #pragma unroll
            for (int v = 0; v < 4; v++) acc[i][j][v] = 0.0f;

    const int NCH = KTOT / 64;
    for (int ch = 0; ch < NCH; ch++) {
        if (ch) __syncthreads();
        const int k0 = ch * 64;
        // ---- A: 128 rows x 64 fp32 -> bf16 hi/lo, SW128 swizzled ----
        #pragma unroll
        for (int i = 0; i < 4; i++) {
            int unit = i * 256 + tid;             // 1024 units of 8 floats
            int r = unit >> 3, c8 = (unit & 7) << 3;
            const float* p = A + (size_t)(row0 + r) * KTOT + k0 + c8;
            float4 v0 = *reinterpret_cast<const float4*>(p);
            float4 v1 = *reinterpret_cast<const float4*>(p + 4);
            float f[8] = {v0.x, v0.y, v0.z, v0.w, v1.x, v1.y, v1.z, v1.w};
            uint32_t hw[8], lw[8];
            #pragma unroll
            for (int j = 0; j < 8; j++) {
                __nv_bfloat16 hb = __float2bfloat16(f[j]);
                __nv_bfloat16 lb = __float2bfloat16(f[j] - __bfloat162float(hb));
                hw[j] = (uint32_t)__bfloat16_as_ushort(hb);
                lw[j] = (uint32_t)__bfloat16_as_ushort(lb);
            }
            uint4 hv, lv;
            hv.x = hw[0] | (hw[1] << 16); hv.y = hw[2] | (hw[3] << 16);
            hv.z = hw[4] | (hw[5] << 16); hv.w = hw[6] | (hw[7] << 16);
            lv.x = lw[0] | (lw[1] << 16); lv.y = lw[2] | (lw[3] << 16);
            lv.z = lw[4] | (lw[5] << 16); lv.w = lw[6] | (lw[7] << 16);
            uint32_t off = SWZ128((uint32_t)(r * 128 + c8 * 2));
            *reinterpret_cast<uint4*>(smem + off)         = hv;
            *reinterpret_cast<uint4*>(smem + 16384 + off) = lv;
        }
        // ---- B: 128 rows x 64 bf16 (hi & lo) -> swizzled ----
        #pragma unroll
        for (int i = 0; i < 4; i++) {
            int unit = i * 256 + tid;
            int r = unit >> 3, u8 = (unit & 7) << 3;
            size_t g = (size_t)(n0 + r) * KTOT + k0 + u8;
            uint4 hv = *reinterpret_cast<const uint4*>(Bhi + g);
            uint4 lv = *reinterpret_cast<const uint4*>(Blo + g);
            uint32_t off = SWZ128((uint32_t)(r * 128 + u8 * 2));
            *reinterpret_cast<uint4*>(smem + 32768 + off) = hv;
            *reinterpret_cast<uint4*>(smem + 49152 + off) = lv;
        }
        __syncthreads();

        // ---- compute: 4 k-steps of 16 ----
        #pragma unroll
        for (int ks = 0; ks < 4; ks++) {
            const int Ck = ks * 16;
            const int l  = lane & 15;   // ldmatrix.x2 uses threads 0-15 addrs
            uint32_t bh[4][2], bl[4][2];
            #pragma unroll
            for (int nt = 0; nt < 4; nt++) {
                uint32_t boff = SWZ128((uint32_t)(
                    (wn * 32 + nt * 8 + (l & 7)) * 128 + (Ck + (l >> 3) * 8) * 2));
                ldsm_x2(bh[nt], sb + 32768 + boff);
                ldsm_x2(bl[nt], sb + 49152 + boff);
            }
            #pragma unroll
            for (int mt = 0; mt < 4; mt++) {
                uint32_t aoff = SWZ128((uint32_t)(
                    (wm * 64 + mt * 16 + (lane & 15)) * 128 + (Ck + (lane >> 4) * 8) * 2));
                uint32_t ah[4], al[4];
                ldsm_x4(ah, sb + aoff);
                ldsm_x4(al, sb + 16384 + aoff);
                #pragma unroll
                for (int nt = 0; nt < 4; nt++) {
                    mma_bf16(acc[mt][nt], ah, bh[nt]);
                    mma_bf16(acc[mt][nt], ah, bl[nt]);
                    mma_bf16(acc[mt][nt], al, bh[nt]);
                }
            }
        }
    }

    // ---- epilogue: direct float2 stores (32B sectors fully covered) ----
    const int gr = lane >> 2;
    const int cp = (lane & 3) * 2;
    #pragma unroll
    for (int mt = 0; mt < 4; mt++) {
        #pragma unroll
        for (int nt = 0; nt < 4; nt++) {
            int row = row0 + wm * 64 + mt * 16 + gr;
            int col = n0 + wn * 32 + nt * 8 + cp;
            size_t g0 = (size_t)row * NOUT + col;
            size_t g1 = (size_t)(row + 8) * NOUT + col;
            float2 v0 = {acc[mt][nt][0], acc[mt][nt][1]};
            float2 v1 = {acc[mt][nt][2], acc[mt][nt][3]};
            if (ADD_SRC) {
                float2 s0 = *reinterpret_cast<const float2*>(Csrc + g0);
                float2 s1 = *reinterpret_cast<const float2*>(Csrc + g1);
                v0.x += s0.x; v0.y += s0.y;
                v1.x += s1.x; v1.y += s1.y;
            }
            *reinterpret_cast<float2*>(C + g0) = v0;
            *reinterpret_cast<float2*>(C + g1) = v1;
        }
    }
}

// ---------------------------------------------------------------------------
// Spline kernel: one block per sample, 256 threads = components
// ---------------------------------------------------------------------------
__global__ __launch_bounds__(NCOMP_C)
void spline_kernel(float* __restrict__ x_io,
                   const int* __restrict__ label,
                   const float* __restrict__ kx,
                   const float* __restrict__ ky,
                   const float* __restrict__ kd,
                   float* __restrict__ logj)
{
    const int n = blockIdx.x;
    const int d = threadIdx.x;
    const int c = label[n];

    const size_t base = ((size_t)c * NCOMP_C + d) * NBIN_C;
    const float* xr = kx + base;
    const float* yr = ky + base;
    const float* dr = kd + base;

    const size_t elem = (size_t)n * NCOMP_C + d;
    const float x = x_io[elem];

    int lo = 0, hi = NBIN_C;
    while (lo < hi) {
        int mid = (lo + hi) >> 1;
        if (__ldg(xr + mid) < x) lo = mid + 1; else hi = mid;
    }

    float y, ld;
    if (lo == 0) {
        float x0 = __ldg(xr), y0 = __ldg(yr), dd = __ldg(dr);
        y  = y0 + dd * (x - x0);
        ld = __logf(dd);
    } else if (lo == NBIN_C) {
        float x1 = __ldg(xr + NBIN_C - 1), y1 = __ldg(yr + NBIN_C - 1),
              dd = __ldg(dr + NBIN_C - 1);
        y  = y1 + dd * (x - x1);
        ld = __logf(dd);
    } else {
        int k = lo - 1;
        float x0 = __ldg(xr + k), x1 = __ldg(xr + k + 1);
        float y0 = __ldg(yr + k), y1 = __ldg(yr + k + 1);
        float d0 = __ldg(dr + k), d1 = __ldg(dr + k + 1);
        float w  = x1 - x0;
        float s  = (y1 - y0) / w;
        float xi = (x - x0) / w;
        xi = fminf(fmaxf(xi, 0.0f), 1.0f);
        float xi1 = 1.0f - xi;
        float t   = xi * xi1;
        float denom = s + (d0 + d1 - 2.0f * s) * t;
        float num   = s * xi * xi + d0 * t;
        y = y0 + (y1 - y0) * num / denom;
        float num2 = d1 * xi * xi + 2.0f * s * t + d0 * xi1 * xi1;
        ld = __logf(s * s * num2 / (denom * denom));
    }

    x_io[elem] = y - x;

    __shared__ float red[8];
    #pragma unroll
    for (int off = 16; off; off >>= 1)
        ld += __shfl_down_sync(0xffffffffu, ld, off);
    if ((d & 31) == 0) red[d >> 5] = ld;
    __syncthreads();
    if (d < 8) {
        float v = red[d];
        #pragma unroll
        for (int off = 4; off; off >>= 1)
            v += __shfl_down_sync(0xffu, v, off);
        if (d == 0) logj[n] = v;
    }
}

// ---------------------------------------------------------------------------
extern "C" void kernel_launch(void* const* d_in, const int* in_sizes, int n_in,
                              void* d_out, int out_size)
{
    const float* data  = (const float*)d_in[0];   // (N, 512)
    const float* wT    = (const float*)d_in[1];   // (512, 256)
    const float* kx    = (const float*)d_in[2];
    const float* ky    = (const float*)d_in[3];
    const float* kd    = (const float*)d_in[4];
    const int*   label = (const int*)d_in[5];

    float* out  = (float*)d_out;
    float* logj = out + (size_t)N_SAMP * NDIM_C;

    float* scratch = nullptr;
    cudaGetSymbolAddress((void**)&scratch, g_scratch);
    __nv_bfloat16 *bt_hi, *bt_lo, *b2_hi, *b2_lo;
    cudaGetSymbolAddress((void**)&bt_hi, g_Bt_hi);
    cudaGetSymbolAddress((void**)&bt_lo, g_Bt_lo);
    cudaGetSymbolAddress((void**)&b2_hi, g_B2_hi);
    cudaGetSymbolAddress((void**)&b2_lo, g_B2_lo);

    cudaFuncSetAttribute(hmma_gemm<NDIM_C, NCOMP_C, false>,
                         cudaFuncAttributeMaxDynamicSharedMemorySize, SMEM_BYTES);
    cudaFuncSetAttribute(hmma_gemm<NCOMP_C, NDIM_C, true>,
                         cudaFuncAttributeMaxDynamicSharedMemorySize, SMEM_BYTES);

    // 0) split wT into bf16 hi/lo (both layouts)
    prep_split<<<(NDIM_C * NCOMP_C) / 256, 256>>>(wT);

    // 1) data0 = data @ wT   (M=131072, N=256, K=512)
    hmma_gemm<NDIM_C, NCOMP_C, false>
        <<<dim3(NCOMP_C / 128, N_SAMP / 128), 256, SMEM_BYTES>>>(
            data, bt_hi, bt_lo, nullptr, scratch);

    // 2) delta = spline(data0) - data0 ; logj
    spline_kernel<<<N_SAMP, NCOMP_C>>>(scratch, label, kx, ky, kd, logj);

    // 3) out = data + delta @ wT.T  (M=131072, N=512, K=256)
    hmma_gemm<NCOMP_C, NDIM_C, true>
        <<<dim3(NDIM_C / 128, N_SAMP / 128), 256, SMEM_BYTES>>>(
            scratch, b2_hi, b2_lo, data, out);
}

// round 8
// speedup vs baseline: 3.5559x; 1.1508x over previous
#include <cuda_runtime.h>
#include <cuda_bf16.h>
#include <cstdint>

#define N_SAMP 131072
#define NDIM_C 512
#define NCOMP_C 256
#define NCLASS_C 8
#define NBIN_C 100
#define SPB 64          // spline blocks per class

// ---------------- device globals (no runtime allocation allowed) ----------
__device__ float g_scratch[(size_t)N_SAMP * NCOMP_C];          // data0 fp32
__device__ __nv_bfloat16 g_dAh[(size_t)N_SAMP * NCOMP_C];      // delta hi
__device__ __nv_bfloat16 g_dAl[(size_t)N_SAMP * NCOMP_C];      // delta lo
__device__ __nv_bfloat16 g_Xh[(size_t)N_SAMP * NDIM_C];        // data hi
__device__ __nv_bfloat16 g_Xl[(size_t)N_SAMP * NDIM_C];        // data lo
// GEMM1 B: [256][512] (wT transposed); GEMM2 B: [512][256] (native)
__device__ __nv_bfloat16 g_Bt_hi[NCOMP_C * NDIM_C];
__device__ __nv_bfloat16 g_Bt_lo[NCOMP_C * NDIM_C];
__device__ __nv_bfloat16 g_B2_hi[NDIM_C * NCOMP_C];
__device__ __nv_bfloat16 g_B2_lo[NDIM_C * NCOMP_C];
// class partition
__device__ int g_cnt[NCLASS_C];
__device__ int g_list[(size_t)NCLASS_C * N_SAMP];
// transposed knot tables: g_xT[c][k][d]; g_ydp[c][k][d] = (y_k,d_k,y_k+1,d_k+1)
__device__ float  g_xT[NCLASS_C * NBIN_C * NCOMP_C];
__device__ float4 g_ydp[NCLASS_C * (NBIN_C - 1) * NCOMP_C];

// ---------------------------------------------------------------------------
__device__ __forceinline__ uint32_t smem_u32(const void* p) {
    uint32_t a;
    asm("{ .reg .u64 t; cvta.to.shared.u64 t, %1; cvt.u32.u64 %0, t; }"
        : "=r"(a) : "l"(p));
    return a;
}
#define SWZ128(off) ((off) ^ (((off) >> 3) & 0x70))

__device__ __forceinline__ void cp16(uint32_t dst, const void* src) {
    asm volatile("cp.async.cg.shared.global [%0], [%1], 16;"
                 :: "r"(dst), "l"(src));
}
__device__ __forceinline__ void cp_commit() {
    asm volatile("cp.async.commit_group;" ::: "memory");
}
__device__ __forceinline__ void cp_wait0() {
    asm volatile("cp.async.wait_group 0;" ::: "memory");
}
__device__ __forceinline__ void ldsm_x4(uint32_t* r, uint32_t addr) {
    asm volatile("ldmatrix.sync.aligned.m8n8.x4.shared.b16 {%0,%1,%2,%3}, [%4];"
                 : "=r"(r[0]), "=r"(r[1]), "=r"(r[2]), "=r"(r[3]) : "r"(addr));
}
__device__ __forceinline__ void ldsm_x2(uint32_t* r, uint32_t addr) {
    asm volatile("ldmatrix.sync.aligned.m8n8.x2.shared.b16 {%0,%1}, [%2];"
                 : "=r"(r[0]), "=r"(r[1]) : "r"(addr));
}
__device__ __forceinline__ void mma_bf16(float* c, const uint32_t* a, const uint32_t* b) {
    asm volatile(
        "mma.sync.aligned.m16n8k16.row.col.f32.bf16.bf16.f32 "
        "{%0,%1,%2,%3}, {%4,%5,%6,%7}, {%8,%9}, {%0,%1,%2,%3};"
        : "+f"(c[0]), "+f"(c[1]), "+f"(c[2]), "+f"(c[3])
        : "r"(a[0]), "r"(a[1]), "r"(a[2]), "r"(a[3]), "r"(b[0]), "r"(b[1]));
}

// ---------------------------------------------------------------------------
// prep kernels
// ---------------------------------------------------------------------------
__global__ void prep_split_w(const float* __restrict__ wT) {
    int i = blockIdx.x * 256 + threadIdx.x;      // over 512*256
    float v = wT[i];
    __nv_bfloat16 h = __float2bfloat16(v);
    __nv_bfloat16 l = __float2bfloat16(v - __bfloat162float(h));
    g_B2_hi[i] = h;  g_B2_lo[i] = l;
    int k = i >> 8, n = i & 255;
    g_Bt_hi[n * NDIM_C + k] = h;
    g_Bt_lo[n * NDIM_C + k] = l;
}

__global__ void split_data(const float* __restrict__ X) {
    size_t i = ((size_t)blockIdx.x * 256 + threadIdx.x) * 4;   // over N*512
    float4 v = *reinterpret_cast<const float4*>(X + i);
    float f[4] = {v.x, v.y, v.z, v.w};
    uint32_t hw[4], lw[4];
    #pragma unroll
    for (int j = 0; j < 4; j++) {
        __nv_bfloat16 hb = __float2bfloat16(f[j]);
        __nv_bfloat16 lb = __float2bfloat16(f[j] - __bfloat162float(hb));
        hw[j] = (uint32_t)__bfloat16_as_ushort(hb);
        lw[j] = (uint32_t)__bfloat16_as_ushort(lb);
    }
    uint2 hv = {hw[0] | (hw[1] << 16), hw[2] | (hw[3] << 16)};
    uint2 lv = {lw[0] | (lw[1] << 16), lw[2] | (lw[3] << 16)};
    *reinterpret_cast<uint2*>(g_Xh + i) = hv;
    *reinterpret_cast<uint2*>(g_Xl + i) = lv;
}

__global__ void k_zero() { if (threadIdx.x < NCLASS_C) g_cnt[threadIdx.x] = 0; }

__global__ void k_classify(const int* __restrict__ label) {
    int n = blockIdx.x * 256 + threadIdx.x;
    int c = label[n];
    int slot = atomicAdd(&g_cnt[c], 1);
    g_list[(size_t)c * N_SAMP + slot] = n;
}

__global__ void k_tables(const float* __restrict__ kx,
                         const float* __restrict__ ky,
                         const float* __restrict__ kd) {
    int i = blockIdx.x * 256 + threadIdx.x;       // 8*100*256
    int d = i & 255, rest = i >> 8;
    int k = rest % NBIN_C, c = rest / NBIN_C;
    size_t src = ((size_t)c * NCOMP_C + d) * NBIN_C + k;
    g_xT[(c * NBIN_C + k) * NCOMP_C + d] = kx[src];
    if (k < NBIN_C - 1)
        g_ydp[((size_t)c * (NBIN_C - 1) + k) * NCOMP_C + d] =
            make_float4(ky[src], kd[src], ky[src + 1], kd[src + 1]);
}

// ---------------------------------------------------------------------------
// Double-buffered HMMA GEMM. All operands bf16 (pre-split hi/lo).
// C[M,NOUT](fp32) = Ahi@B^T products (3-term split), optional += Csrc.
// Block tile 128(M) x 64(N), K-chunk 64, 2-stage cp.async pipeline.
// 256 threads = 8 warps: 4 along M (32 rows), 2 along N (32 cols).
// ---------------------------------------------------------------------------
static constexpr int STAGE = 49152;                 // Ahi16K|Alo16K|Bhi8K|Blo8K
static constexpr int GEMM_SMEM = 2 * STAGE;         // 96KB -> 2 CTAs/SM

template<int KTOT, int NOUT, bool ADD_SRC>
__global__ __launch_bounds__(256, 2)
void gemm_db(const __nv_bfloat16* __restrict__ Ahi,
             const __nv_bfloat16* __restrict__ Alo,
             const __nv_bfloat16* __restrict__ Bhi,
             const __nv_bfloat16* __restrict__ Blo,
             const float* __restrict__ Csrc,
             float* __restrict__ C)
{
    extern __shared__ char smem[];
    const uint32_t sb = smem_u32(smem);
    const int tid  = threadIdx.x;
    const int lane = tid & 31;
    const int wid  = tid >> 5;
    const int wm   = wid & 3;           // 4 warps along M
    const int wn   = wid >> 2;          // 2 warps along N
    const int row0 = blockIdx.y * 128;
    const int n0   = blockIdx.x * 64;

    auto load_stage = [&](int ch, int s) {
        const uint32_t st = sb + s * STAGE;
        const int k0 = ch * 64;
        #pragma unroll
        for (int i = 0; i < 4; i++) {                       // A: 1024 units
            int unit = i * 256 + tid;
            int r = unit >> 3, u8 = (unit & 7) << 3;
            uint32_t off = SWZ128((uint32_t)(r * 128 + u8 * 2));
            size_t g = (size_t)(row0 + r) * KTOT + k0 + u8;
            cp16(st + off,         Ahi + g);
            cp16(st + 16384 + off, Alo + g);
        }
        #pragma unroll
        for (int i = 0; i < 2; i++) {                       // B: 512 units
            int unit = i * 256 + tid;
            int r = unit >> 3, u8 = (unit & 7) << 3;
            uint32_t off = SWZ128((uint32_t)(r * 128 + u8 * 2));
            size_t g = (size_t)(n0 + r) * KTOT + k0 + u8;
            cp16(st + 32768 + off, Bhi + g);
            cp16(st + 40960 + off, Blo + g);
        }
        cp_commit();
    };

    float acc[2][4][4];
    #pragma unroll
    for (int i = 0; i < 2; i++)
        #pragma unroll
        for (int j = 0; j < 4; j++)
            #pragma unroll
            for (int v = 0; v < 4; v++) acc[i][j][v] = 0.0f;

    const int NCH = KTOT / 64;
    load_stage(0, 0);
    cp_wait0();
    __syncthreads();

    for (int ch = 0; ch < NCH; ch++) {
        const int s = ch & 1;
        if (ch + 1 < NCH) load_stage(ch + 1, s ^ 1);  // async into other stage

        const uint32_t st = sb + s * STAGE;
        #pragma unroll
        for (int ks = 0; ks < 4; ks++) {
            const int Ck = ks * 16;
            const int l  = lane & 15;
            uint32_t bh[4][2], bl[4][2];
            #pragma unroll
            for (int nt = 0; nt < 4; nt++) {
                uint32_t boff = SWZ128((uint32_t)(
                    (wn * 32 + nt * 8 + (l & 7)) * 128 + (Ck + (l >> 3) * 8) * 2));
                ldsm_x2(bh[nt], st + 32768 + boff);
                ldsm_x2(bl[nt], st + 40960 + boff);
            }
            #pragma unroll
            for (int mt = 0; mt < 2; mt++) {
                uint32_t aoff = SWZ128((uint32_t)(
                    (wm * 32 + mt * 16 + (lane & 15)) * 128 + (Ck + (lane >> 4) * 8) * 2));
                uint32_t ah[4], al[4];
                ldsm_x4(ah, st + aoff);
                ldsm_x4(al, st + 16384 + aoff);
                #pragma unroll
                for (int nt = 0; nt < 4; nt++) {
                    mma_bf16(acc[mt][nt], ah, bh[nt]);
                    mma_bf16(acc[mt][nt], ah, bl[nt]);
                    mma_bf16(acc[mt][nt], al, bh[nt]);
                }
            }
        }
        if (ch + 1 < NCH) cp_wait0();
        __syncthreads();
    }

    // epilogue: direct float2 stores
    const int gr = lane >> 2;
    const int cp = (lane & 3) * 2;
    #pragma unroll
    for (int mt = 0; mt < 2; mt++) {
        #pragma unroll
        for (int nt = 0; nt < 4; nt++) {
            int row = row0 + wm * 32 + mt * 16 + gr;
            int col = n0 + wn * 32 + nt * 8 + cp;
            size_t g0 = (size_t)row * NOUT + col;
            size_t g1 = (size_t)(row + 8) * NOUT + col;
            float2 v0 = {acc[mt][nt][0], acc[mt][nt][1]};
            float2 v1 = {acc[mt][nt][2], acc[mt][nt][3]};
            if (ADD_SRC) {
                float2 s0 = *reinterpret_cast<const float2*>(Csrc + g0);
                float2 s1 = *reinterpret_cast<const float2*>(Csrc + g1);
                v0.x += s0.x; v0.y += s0.y;
                v1.x += s1.x; v1.y += s1.y;
            }
            *reinterpret_cast<float2*>(C + g0) = v0;
            *reinterpret_cast<float2*>(C + g1) = v1;
        }
    }
}

// ---------------------------------------------------------------------------
// Class-partitioned spline: grid (SPB, NCLASS). Block caches the class's
// transposed x-knot table in smem (100KB); binary search runs in smem,
// (y,d) pairs come as one float4 gmem load. Emits delta as bf16 hi/lo.
// 2 samples per thread for ILP.
// ---------------------------------------------------------------------------
static constexpr int SPLINE_SMEM = NBIN_C * NCOMP_C * 4;   // 102400

__global__ __launch_bounds__(NCOMP_C)
void spline_kernel(const float* __restrict__ x_in,
                   float* __restrict__ logj)
{
    extern __shared__ float xs[];                     // [100][256]
    __shared__ float red[16];
    const int c   = blockIdx.y;
    const int tid = threadIdx.x;
    const int lane = tid & 31, wid = tid >> 5;

    // load x table (coalesced float4)
    {
        const float4* src = reinterpret_cast<const float4*>(
            g_xT + (size_t)c * NBIN_C * NCOMP_C);
        float4* dst = reinterpret_cast<float4*>(xs);
        #pragma unroll
        for (int i = 0; i < 25; i++) dst[i * 256 + tid] = src[i * 256 + tid];
    }
    __syncthreads();

    const int cnt = g_cnt[c];
    const int* lst = g_list + (size_t)c * N_SAMP;
    const float4* ydp = g_ydp + (size_t)c * (NBIN_C - 1) * NCOMP_C;

    for (int i = blockIdx.x * 2; i < cnt; i += SPB * 2) {
        const int n0 = lst[i];
        const int n1 = lst[min(i + 1, cnt - 1)];
        const int nn[2] = {n0, n1};
        float xv[2];
        xv[0] = x_in[(size_t)n0 * NCOMP_C + tid];
        xv[1] = x_in[(size_t)n1 * NCOMP_C + tid];

        int lo[2] = {0, 0}, hi[2] = {NBIN_C, NBIN_C};
        #pragma unroll
        for (int stp = 0; stp < 7; stp++) {
            #pragma unroll
            for (int j = 0; j < 2; j++) {
                if (lo[j] < hi[j]) {
                    int mid = (lo[j] + hi[j]) >> 1;
                    if (xs[mid * NCOMP_C + tid] < xv[j]) lo[j] = mid + 1;
                    else hi[j] = mid;
                }
            }
        }

        float ldv[2];
        #pragma unroll
        for (int j = 0; j < 2; j++) {
            const int L = lo[j];
            const int kk = (L == 0) ? 0 : ((L == NBIN_C) ? NBIN_C - 2 : L - 1);
            const float xlo = xs[kk * NCOMP_C + tid];
            const float xhi = xs[(kk + 1) * NCOMP_C + tid];
            const float4 f4 = __ldg(&ydp[(size_t)kk * NCOMP_C + tid]);
            const float x = xv[j];
            float y, ld;
            if (L == 0) {
                y = f4.x + f4.y * (x - xlo);  ld = __logf(f4.y);
            } else if (L == NBIN_C) {
                y = f4.z + f4.w * (x - xhi);  ld = __logf(f4.w);
            } else {
                float w  = xhi - xlo;
                float s  = (f4.z - f4.x) / w;
                float xi = fminf(fmaxf((x - xlo) / w, 0.0f), 1.0f);
                float xi1 = 1.0f - xi;
                float t   = xi * xi1;
                float denom = s + (f4.y + f4.w - 2.0f * s) * t;
                y = f4.x + (f4.z - f4.x) * (s * xi * xi + f4.y * t) / denom;
                float num2 = f4.w * xi * xi + 2.0f * s * t + f4.y * xi1 * xi1;
                ld = __logf(s * s * num2 / (denom * denom));
            }
            // delta split to bf16 hi/lo
            float dta = y - x;
            __nv_bfloat16 h = __float2bfloat16(dta);
            __nv_bfloat16 lw = __float2bfloat16(dta - __bfloat162float(h));
            g_dAh[(size_t)nn[j] * NCOMP_C + tid] = h;
            g_dAl[(size_t)nn[j] * NCOMP_C + tid] = lw;
            ldv[j] = ld;
        }

        // deterministic two-stage reduction for logj
        #pragma unroll
        for (int j = 0; j < 2; j++) {
            float v = ldv[j];
            #pragma unroll
            for (int off = 16; off; off >>= 1)
                v += __shfl_down_sync(0xffffffffu, v, off);
            if (lane == 0) red[j * 8 + wid] = v;
        }
        __syncthreads();
        if (tid < 16) {
            float v = red[tid];
            v += __shfl_down_sync(0xffffu, v, 4, 8);
            v += __shfl_down_sync(0xffffu, v, 2, 8);
            v += __shfl_down_sync(0xffffu, v, 1, 8);
            if (tid == 0) logj[n0] = v;
            if (tid == 8) logj[n1] = v;
        }
        __syncthreads();
    }
}

// ---------------------------------------------------------------------------
extern "C" void kernel_launch(void* const* d_in, const int* in_sizes, int n_in,
                              void* d_out, int out_size)
{
    const float* data  = (const float*)d_in[0];   // (N, 512)
    const float* wT    = (const float*)d_in[1];   // (512, 256)
    const float* kx    = (const float*)d_in[2];
    const float* ky    = (const float*)d_in[3];
    const float* kd    = (const float*)d_in[4];
    const int*   label = (const int*)d_in[5];

    float* out  = (float*)d_out;
    float* logj = out + (size_t)N_SAMP * NDIM_C;

    float* scratch = nullptr;
    cudaGetSymbolAddress((void**)&scratch, g_scratch);
    __nv_bfloat16 *xh, *xl, *dah, *dal, *bt_hi, *bt_lo, *b2_hi, *b2_lo;
    cudaGetSymbolAddress((void**)&xh, g_Xh);
    cudaGetSymbolAddress((void**)&xl, g_Xl);
    cudaGetSymbolAddress((void**)&dah, g_dAh);
    cudaGetSymbolAddress((void**)&dal, g_dAl);
    cudaGetSymbolAddress((void**)&bt_hi, g_Bt_hi);
    cudaGetSymbolAddress((void**)&bt_lo, g_Bt_lo);
    cudaGetSymbolAddress((void**)&b2_hi, g_B2_hi);
    cudaGetSymbolAddress((void**)&b2_lo, g_B2_lo);

    cudaFuncSetAttribute(gemm_db<NDIM_C, NCOMP_C, false>,
                         cudaFuncAttributeMaxDynamicSharedMemorySize, GEMM_SMEM);
    cudaFuncSetAttribute(gemm_db<NCOMP_C, NDIM_C, true>,
                         cudaFuncAttributeMaxDynamicSharedMemorySize, GEMM_SMEM);
    cudaFuncSetAttribute(spline_kernel,
                         cudaFuncAttributeMaxDynamicSharedMemorySize, SPLINE_SMEM);

    // prep
    prep_split_w<<<(NDIM_C * NCOMP_C) / 256, 256>>>(wT);
    split_data<<<(int)(((size_t)N_SAMP * NDIM_C / 4) / 256), 256>>>(data);
    k_zero<<<1, 32>>>();
    k_classify<<<N_SAMP / 256, 256>>>(label);
    k_tables<<<(NCLASS_C * NBIN_C * NCOMP_C) / 256, 256>>>(kx, ky, kd);

    // 1) data0 = data @ wT   (M=131072, N=256, K=512)
    gemm_db<NDIM_C, NCOMP_C, false>
        <<<dim3(NCOMP_C / 64, N_SAMP / 128), 256, GEMM_SMEM>>>(
            xh, xl, bt_hi, bt_lo, nullptr, scratch);

    // 2) spline: delta (bf16 hi/lo) + logj
    spline_kernel<<<dim3(SPB, NCLASS_C), NCOMP_C, SPLINE_SMEM>>>(scratch, logj);

    // 3) out = data + delta @ wT.T  (M=131072, N=512, K=256)
    gemm_db<NCOMP_C, NDIM_C, true>
        <<<dim3(NDIM_C / 64, N_SAMP / 128), 256, GEMM_SMEM>>>(
            dah, dal, b2_hi, b2_lo, data, out);
}

// round 11
// speedup vs baseline: 3.7534x; 1.0555x over previous
#include <cuda_runtime.h>
#include <cuda_bf16.h>
#include <cstdint>

#define N_SAMP 131072
#define NDIM_C 512
#define NCOMP_C 256
#define NCLASS_C 8
#define NBIN_C 100
#define SPB 64          // spline blocks per class

// ---------------- device globals (no runtime allocation allowed) ----------
__device__ float g_scratch[(size_t)N_SAMP * NCOMP_C];          // data0 fp32
__device__ __nv_bfloat16 g_dAh[(size_t)N_SAMP * NCOMP_C];      // delta hi
__device__ __nv_bfloat16 g_dAl[(size_t)N_SAMP * NCOMP_C];      // delta lo
__device__ __nv_bfloat16 g_Xh[(size_t)N_SAMP * NDIM_C];        // data hi
__device__ __nv_bfloat16 g_Xl[(size_t)N_SAMP * NDIM_C];        // data lo
// GEMM1 B: [256][512] (wT transposed); GEMM2 B: [512][256] (native)
__device__ __nv_bfloat16 g_Bt_hi[NCOMP_C * NDIM_C];
__device__ __nv_bfloat16 g_Bt_lo[NCOMP_C * NDIM_C];
__device__ __nv_bfloat16 g_B2_hi[NDIM_C * NCOMP_C];
__device__ __nv_bfloat16 g_B2_lo[NDIM_C * NCOMP_C];
// class partition
__device__ int g_cnt[NCLASS_C];
__device__ int g_list[(size_t)NCLASS_C * N_SAMP];
// transposed knot tables: g_xT[c][k][d]; g_ydp[c][k][d] = (y_k,d_k,y_k+1,d_k+1)
__device__ float  g_xT[NCLASS_C * NBIN_C * NCOMP_C];
__device__ float4 g_ydp[NCLASS_C * (NBIN_C - 1) * NCOMP_C];

// ---------------------------------------------------------------------------
__device__ __forceinline__ uint32_t smem_u32(const void* p) {
    uint32_t a;
    asm("{ .reg .u64 t; cvta.to.shared.u64 t, %1; cvt.u32.u64 %0, t; }"
        : "=r"(a) : "l"(p));
    return a;
}
#define SWZ128(off) ((off) ^ (((off) >> 3) & 0x70))

__device__ __forceinline__ void cp16(uint32_t dst, const void* src) {
    asm volatile("cp.async.cg.shared.global [%0], [%1], 16;"
                 :: "r"(dst), "l"(src));
}
__device__ __forceinline__ void cp_commit() {
    asm volatile("cp.async.commit_group;" ::: "memory");
}
__device__ __forceinline__ void cp_wait0() {
    asm volatile("cp.async.wait_group 0;" ::: "memory");
}
__device__ __forceinline__ void ldsm_x4(uint32_t* r, uint32_t addr) {
    asm volatile("ldmatrix.sync.aligned.m8n8.x4.shared.b16 {%0,%1,%2,%3}, [%4];"
                 : "=r"(r[0]), "=r"(r[1]), "=r"(r[2]), "=r"(r[3]) : "r"(addr));
}
__device__ __forceinline__ void mma_bf16(float* c, const uint32_t* a, const uint32_t* b) {
    asm volatile(
        "mma.sync.aligned.m16n8k16.row.col.f32.bf16.bf16.f32 "
        "{%0,%1,%2,%3}, {%4,%5,%6,%7}, {%8,%9}, {%0,%1,%2,%3};"
        : "+f"(c[0]), "+f"(c[1]), "+f"(c[2]), "+f"(c[3])
        : "r"(a[0]), "r"(a[1]), "r"(a[2]), "r"(a[3]), "r"(b[0]), "r"(b[1]));
}

// ---------------------------------------------------------------------------
// prep kernels
// ---------------------------------------------------------------------------
__global__ void prep_split_w(const float* __restrict__ wT) {
    int i = blockIdx.x * 256 + threadIdx.x;      // over 512*256
    float v = wT[i];
    __nv_bfloat16 h = __float2bfloat16(v);
    __nv_bfloat16 l = __float2bfloat16(v - __bfloat162float(h));
    g_B2_hi[i] = h;  g_B2_lo[i] = l;
    int k = i >> 8, n = i & 255;
    g_Bt_hi[n * NDIM_C + k] = h;
    g_Bt_lo[n * NDIM_C + k] = l;
}

__global__ void split_data(const float* __restrict__ X) {
    size_t i = ((size_t)blockIdx.x * 256 + threadIdx.x) * 4;   // over N*512
    float4 v = *reinterpret_cast<const float4*>(X + i);
    float f[4] = {v.x, v.y, v.z, v.w};
    uint32_t hw[4], lw[4];
    #pragma unroll
    for (int j = 0; j < 4; j++) {
        __nv_bfloat16 hb = __float2bfloat16(f[j]);
        __nv_bfloat16 lb = __float2bfloat16(f[j] - __bfloat162float(hb));
        hw[j] = (uint32_t)__bfloat16_as_ushort(hb);
        lw[j] = (uint32_t)__bfloat16_as_ushort(lb);
    }
    uint2 hv = {hw[0] | (hw[1] << 16), hw[2] | (hw[3] << 16)};
    uint2 lv = {lw[0] | (lw[1] << 16), lw[2] | (lw[3] << 16)};
    *reinterpret_cast<uint2*>(g_Xh + i) = hv;
    *reinterpret_cast<uint2*>(g_Xl + i) = lv;
}

__global__ void k_zero() { if (threadIdx.x < NCLASS_C) g_cnt[threadIdx.x] = 0; }

// smem-histogram classify: 8 global atomics per block instead of 256
__global__ void k_classify(const int* __restrict__ label) {
    __shared__ int h[NCLASS_C], base[NCLASS_C];
    const int n = blockIdx.x * 256 + threadIdx.x;
    if (threadIdx.x < NCLASS_C) h[threadIdx.x] = 0;
    __syncthreads();
    const int c = label[n];
    const int my = atomicAdd(&h[c], 1);
    __syncthreads();
    if (threadIdx.x < NCLASS_C)
        base[threadIdx.x] = atomicAdd(&g_cnt[threadIdx.x], h[threadIdx.x]);
    __syncthreads();
    g_list[(size_t)c * N_SAMP + base[c] + my] = n;
}

__global__ void k_tables(const float* __restrict__ kx,
                         const float* __restrict__ ky,
                         const float* __restrict__ kd) {
    int i = blockIdx.x * 256 + threadIdx.x;       // 8*100*256
    int d = i & 255, rest = i >> 8;
    int k = rest % NBIN_C, c = rest / NBIN_C;
    size_t src = ((size_t)c * NCOMP_C + d) * NBIN_C + k;
    g_xT[(c * NBIN_C + k) * NCOMP_C + d] = kx[src];
    if (k < NBIN_C - 1)
        g_ydp[((size_t)c * (NBIN_C - 1) + k) * NCOMP_C + d] =
            make_float4(ky[src], kd[src], ky[src + 1], kd[src + 1]);
}

// ---------------------------------------------------------------------------
// Big-tile double-buffered HMMA GEMM: 128(M) x 128(N), K-chunk 64, 2 stages.
// 256 threads = 8 warps: 4 along M (32 rows) x 2 along N (64 cols).
// Per k16-step per warp: 48 MMAs per 12 ldsm -> 2x the tensor density of the
// previous 128x64 tile. 128KB smem, 1 CTA/SM, registers uncapped.
// 3-product split precision: Ahi*Bhi + Ahi*Blo + Alo*Bhi, fp32 accumulate.
// ---------------------------------------------------------------------------
static constexpr int STAGE = 65536;              // Ahi16K|Alo16K|Bhi16K|Blo16K
static constexpr int GEMM_SMEM = 2 * STAGE;      // 128KB

template<int KTOT, int NOUT, bool ADD_SRC>
__global__ __launch_bounds__(256, 1)
void gemm_big(const __nv_bfloat16* __restrict__ Ahi,
              const __nv_bfloat16* __restrict__ Alo,
              const __nv_bfloat16* __restrict__ Bhi,
              const __nv_bfloat16* __restrict__ Blo,
              const float* __restrict__ Csrc,
              float* __restrict__ C)
{
    extern __shared__ char smem[];
    const uint32_t sb = smem_u32(smem);
    const int tid  = threadIdx.x;
    const int lane = tid & 31;
    const int wid  = tid >> 5;
    const int wm   = wid & 3;           // 4 warps along M (32 rows)
    const int wn   = wid >> 2;          // 2 warps along N (64 cols)
    const int row0 = blockIdx.y * 128;
    const int n0   = blockIdx.x * 128;

    auto load_stage = [&](int ch, int s) {
        const uint32_t st = sb + s * STAGE;
        const int k0 = ch * 64;
        #pragma unroll
        for (int i = 0; i < 4; i++) {                       // A: 1024 units
            int unit = i * 256 + tid;
            int r = unit >> 3, u8 = (unit & 7) << 3;
            uint32_t off = SWZ128((uint32_t)(r * 128 + u8 * 2));
            size_t g = (size_t)(row0 + r) * KTOT + k0 + u8;
            cp16(st + off,         Ahi + g);
            cp16(st + 16384 + off, Alo + g);
        }
        #pragma unroll
        for (int i = 0; i < 4; i++) {                       // B: 1024 units
            int unit = i * 256 + tid;
            int r = unit >> 3, u8 = (unit & 7) << 3;
            uint32_t off = SWZ128((uint32_t)(r * 128 + u8 * 2));
            size_t g = (size_t)(n0 + r) * KTOT + k0 + u8;
            cp16(st + 32768 + off, Bhi + g);
            cp16(st + 49152 + off, Blo + g);
        }
        cp_commit();
    };

    float acc[2][8][4];
    #pragma unroll
    for (int i = 0; i < 2; i++)
        #pragma unroll
        for (int j = 0; j < 8; j++)
            #pragma unroll
            for (int v = 0; v < 4; v++) acc[i][j][v] = 0.0f;

    const int NCH = KTOT / 64;
    load_stage(0, 0);
    cp_wait0();
    __syncthreads();

    for (int ch = 0; ch < NCH; ch++) {
        const int s = ch & 1;
        if (ch + 1 < NCH) load_stage(ch + 1, s ^ 1);

        const uint32_t st = sb + s * STAGE;
        #pragma unroll
        for (int ks = 0; ks < 4; ks++) {
            const int Ck = ks * 16;
            // A fragments: 2 m16 tiles, hi & lo
            uint32_t ah[2][4], al[2][4];
            #pragma unroll
            for (int mt = 0; mt < 2; mt++) {
                uint32_t aoff = SWZ128((uint32_t)(
                    (wm * 32 + mt * 16 + (lane & 15)) * 128 + (Ck + (lane >> 4) * 8) * 2));
                ldsm_x4(ah[mt], st + aoff);
                ldsm_x4(al[mt], st + 16384 + aoff);
            }
            // B: pairs of n8 tiles via single ldsm_x4
            #pragma unroll
            for (int p = 0; p < 4; p++) {
                uint32_t boff = SWZ128((uint32_t)(
                    (wn * 64 + p * 16 + ((lane >> 4) << 3) + (lane & 7)) * 128 +
                    (Ck + ((lane >> 3) & 1) * 8) * 2));
                uint32_t bh4[4], bl4[4];
                ldsm_x4(bh4, st + 32768 + boff);
                ldsm_x4(bl4, st + 49152 + boff);
                #pragma unroll
                for (int hf = 0; hf < 2; hf++) {
                    const int nt = 2 * p + hf;
                    const uint32_t* bh = bh4 + 2 * hf;
                    const uint32_t* bl = bl4 + 2 * hf;
                    #pragma unroll
                    for (int mt = 0; mt < 2; mt++) {
                        mma_bf16(acc[mt][nt], ah[mt], bh);
                        mma_bf16(acc[mt][nt], ah[mt], bl);
                        mma_bf16(acc[mt][nt], al[mt], bh);
                    }
                }
            }
        }
        if (ch + 1 < NCH) cp_wait0();
        __syncthreads();
    }

    // epilogue: direct float2 stores
    const int gr = lane >> 2;
    const int cp = (lane & 3) * 2;
    #pragma unroll
    for (int mt = 0; mt < 2; mt++) {
        #pragma unroll
        for (int nt = 0; nt < 8; nt++) {
            int row = row0 + wm * 32 + mt * 16 + gr;
            int col = n0 + wn * 64 + nt * 8 + cp;
            size_t g0 = (size_t)row * NOUT + col;
            size_t g1 = (size_t)(row + 8) * NOUT + col;
            float2 v0 = {acc[mt][nt][0], acc[mt][nt][1]};
            float2 v1 = {acc[mt][nt][2], acc[mt][nt][3]};
            if (ADD_SRC) {
                float2 s0 = *reinterpret_cast<const float2*>(Csrc + g0);
                float2 s1 = *reinterpret_cast<const float2*>(Csrc + g1);
                v0.x += s0.x; v0.y += s0.y;
                v1.x += s1.x; v1.y += s1.y;
            }
            *reinterpret_cast<float2*>(C + g0) = v0;
            *reinterpret_cast<float2*>(C + g1) = v1;
        }
    }
}

// ---------------------------------------------------------------------------
// Class-partitioned spline, 4 samples per thread for ILP (hides the 7-deep
// dependent LDS binary-search chain at 1 CTA/SM occupancy).
// ---------------------------------------------------------------------------
static constexpr int SPLINE_SMEM = NBIN_C * NCOMP_C * 4;   // 102400

__global__ __launch_bounds__(NCOMP_C)
void spline_kernel(const float* __restrict__ x_in,
                   float* __restrict__ logj)
{
    extern __shared__ float xs[];                     // [100][256]
    __shared__ float red[32];
    const int c   = blockIdx.y;
    const int tid = threadIdx.x;
    const int lane = tid & 31, wid = tid >> 5;

    // load x table (coalesced float4)
    {
        const float4* src = reinterpret_cast<const float4*>(
            g_xT + (size_t)c * NBIN_C * NCOMP_C);
        float4* dst = reinterpret_cast<float4*>(xs);
        #pragma unroll
        for (int i = 0; i < 25; i++) dst[i * 256 + tid] = src[i * 256 + tid];
    }
    __syncthreads();

    const int cnt = g_cnt[c];
    const int* lst = g_list + (size_t)c * N_SAMP;
    const float4* ydp = g_ydp + (size_t)c * (NBIN_C - 1) * NCOMP_C;

    for (int i = blockIdx.x * 4; i < cnt; i += SPB * 4) {
        int nn[4];
        #pragma unroll
        for (int j = 0; j < 4; j++) nn[j] = lst[min(i + j, cnt - 1)];

        float xv[4];
        #pragma unroll
        for (int j = 0; j < 4; j++)
            xv[j] = x_in[(size_t)nn[j] * NCOMP_C + tid];

        int lo[4] = {0, 0, 0, 0}, hi[4] = {NBIN_C, NBIN_C, NBIN_C, NBIN_C};
        #pragma unroll
        for (int stp = 0; stp < 7; stp++) {
            #pragma unroll
            for (int j = 0; j < 4; j++) {
                if (lo[j] < hi[j]) {
                    int mid = (lo[j] + hi[j]) >> 1;
                    if (xs[mid * NCOMP_C + tid] < xv[j]) lo[j] = mid + 1;
                    else hi[j] = mid;
                }
            }
        }

        float ldv[4];
        #pragma unroll
        for (int j = 0; j < 4; j++) {
            const int L = lo[j];
            const int kk = (L == 0) ? 0 : ((L == NBIN_C) ? NBIN_C - 2 : L - 1);
            const float xlo = xs[kk * NCOMP_C + tid];
            const float xhi = xs[(kk + 1) * NCOMP_C + tid];
            const float4 f4 = __ldg(&ydp[(size_t)kk * NCOMP_C + tid]);
            const float x = xv[j];
            float y, ld;
            if (L == 0) {
                y = f4.x + f4.y * (x - xlo);  ld = __logf(f4.y);
            } else if (L == NBIN_C) {
                y = f4.z + f4.w * (x - xhi);  ld = __logf(f4.w);
            } else {
                float w  = xhi - xlo;
                float s  = (f4.z - f4.x) / w;
                float xi = fminf(fmaxf((x - xlo) / w, 0.0f), 1.0f);
                float xi1 = 1.0f - xi;
                float t   = xi * xi1;
                float denom = s + (f4.y + f4.w - 2.0f * s) * t;
                y = f4.x + (f4.z - f4.x) * (s * xi * xi + f4.y * t) / denom;
                float num2 = f4.w * xi * xi + 2.0f * s * t + f4.y * xi1 * xi1;
                ld = __logf(s * s * num2 / (denom * denom));
            }
            float dta = y - x;
            __nv_bfloat16 h = __float2bfloat16(dta);
            __nv_bfloat16 lw = __float2bfloat16(dta - __bfloat162float(h));
            g_dAh[(size_t)nn[j] * NCOMP_C + tid] = h;
            g_dAl[(size_t)nn[j] * NCOMP_C + tid] = lw;
            ldv[j] = ld;
        }

        // reduction: one sync for 4 samples
        #pragma unroll
        for (int j = 0; j < 4; j++) {
            float v = ldv[j];
            #pragma unroll
            for (int off = 16; off; off >>= 1)
                v += __shfl_down_sync(0xffffffffu, v, off);
            if (lane == 0) red[j * 8 + wid] = v;
        }
        __syncthreads();
        if (tid < 32) {
            float v = red[tid];
            v += __shfl_down_sync(0xffffffffu, v, 4, 8);
            v += __shfl_down_sync(0xffffffffu, v, 2, 8);
            v += __shfl_down_sync(0xffffffffu, v, 1, 8);
            if      (tid == 0)  logj[nn[0]] = v;
            else if (tid == 8)  logj[nn[1]] = v;
            else if (tid == 16) logj[nn[2]] = v;
            else if (tid == 24) logj[nn[3]] = v;
        }
        __syncthreads();
    }
}

// ---------------------------------------------------------------------------
extern "C" void kernel_launch(void* const* d_in, const int* in_sizes, int n_in,
                              void* d_out, int out_size)
{
    const float* data  = (const float*)d_in[0];   // (N, 512)
    const float* wT    = (const float*)d_in[1];   // (512, 256)
    const float* kx    = (const float*)d_in[2];
    const float* ky    = (const float*)d_in[3];
    const float* kd    = (const float*)d_in[4];
    const int*   label = (const int*)d_in[5];

    float* out  = (float*)d_out;
    float* logj = out + (size_t)N_SAMP * NDIM_C;

    float* scratch = nullptr;
    cudaGetSymbolAddress((void**)&scratch, g_scratch);
    __nv_bfloat16 *xh, *xl, *dah, *dal, *bt_hi, *bt_lo, *b2_hi, *b2_lo;
    cudaGetSymbolAddress((void**)&xh, g_Xh);
    cudaGetSymbolAddress((void**)&xl, g_Xl);
    cudaGetSymbolAddress((void**)&dah, g_dAh);
    cudaGetSymbolAddress((void**)&dal, g_dAl);
    cudaGetSymbolAddress((void**)&bt_hi, g_Bt_hi);
    cudaGetSymbolAddress((void**)&bt_lo, g_Bt_lo);
    cudaGetSymbolAddress((void**)&b2_hi, g_B2_hi);
    cudaGetSymbolAddress((void**)&b2_lo, g_B2_lo);

    cudaFuncSetAttribute(gemm_big<NDIM_C, NCOMP_C, false>,
                         cudaFuncAttributeMaxDynamicSharedMemorySize, GEMM_SMEM);
    cudaFuncSetAttribute(gemm_big<NCOMP_C, NDIM_C, true>,
                         cudaFuncAttributeMaxDynamicSharedMemorySize, GEMM_SMEM);
    cudaFuncSetAttribute(spline_kernel,
                         cudaFuncAttributeMaxDynamicSharedMemorySize, SPLINE_SMEM);

    // prep
    prep_split_w<<<(NDIM_C * NCOMP_C) / 256, 256>>>(wT);
    split_data<<<(int)(((size_t)N_SAMP * NDIM_C / 4) / 256), 256>>>(data);
    k_zero<<<1, 32>>>();
    k_classify<<<N_SAMP / 256, 256>>>(label);
    k_tables<<<(NCLASS_C * NBIN_C * NCOMP_C) / 256, 256>>>(kx, ky, kd);

    // 1) data0 = data @ wT   (M=131072, N=256, K=512)
    gemm_big<NDIM_C, NCOMP_C, false>
        <<<dim3(NCOMP_C / 128, N_SAMP / 128), 256, GEMM_SMEM>>>(
            xh, xl, bt_hi, bt_lo, nullptr, scratch);

    // 2) spline: delta (bf16 hi/lo) + logj
    spline_kernel<<<dim3(SPB, NCLASS_C), NCOMP_C, SPLINE_SMEM>>>(scratch, logj);

    // 3) out = data + delta @ wT.T  (M=131072, N=512, K=256)
    gemm_big<NCOMP_C, NDIM_C, true>
        <<<dim3(NDIM_C / 128, N_SAMP / 128), 256, GEMM_SMEM>>>(
            dah, dal, b2_hi, b2_lo, data, out);
}